// round 8
// baseline (speedup 1.0000x reference)
#include <cuda_runtime.h>
#include <cuda_fp16.h>
#include <math.h>
#include <stdint.h>

#define BB 32
#define TT 4096
#define DD 512
#define UU 256

#define APH 72    // As pitch in halves (64 k + 8 pad) -> 144B rows, LDSM conflict-free
#define BPH 72    // Bs pitch in halves

// scratch (no allocations allowed)
__device__ float  g_hq[BB * UU];
__device__ float  g_scores[BB * TT];
__device__ __half g_W1h[UU * DD];   // W1 transposed [u][k], fp16

__device__ __forceinline__ uint32_t smem_u32(const void* p) {
    uint32_t a;
    asm("{ .reg .u64 t; cvta.to.shared.u64 t, %1; cvt.u32.u64 %0, t; }"
        : "=r"(a) : "l"(p));
    return a;
}
__device__ __forceinline__ void cp_async16(uint32_t dst, const void* src) {
    asm volatile("cp.async.cg.shared.global [%0], [%1], 16;"
                 :: "r"(dst), "l"(src) : "memory");
}
__device__ __forceinline__ void cp_commit() {
    asm volatile("cp.async.commit_group;" ::: "memory");
}
__device__ __forceinline__ void cp_wait0() {
    asm volatile("cp.async.wait_group 0;" ::: "memory");
}
__device__ __forceinline__ void mma_f16(float c[4], const uint32_t a[4],
                                        const uint32_t b[2]) {
    asm volatile(
        "mma.sync.aligned.m16n8k16.row.col.f32.f16.f16.f32 "
        "{%0,%1,%2,%3}, {%4,%5,%6,%7}, {%8,%9}, {%0,%1,%2,%3};"
        : "+f"(c[0]), "+f"(c[1]), "+f"(c[2]), "+f"(c[3])
        : "r"(a[0]), "r"(a[1]), "r"(a[2]), "r"(a[3]), "r"(b[0]), "r"(b[1]));
}
__device__ __forceinline__ void ldsm_x4(uint32_t r[4], uint32_t addr) {
    asm volatile("ldmatrix.sync.aligned.m8n8.x4.shared.b16 {%0,%1,%2,%3}, [%4];"
                 : "=r"(r[0]), "=r"(r[1]), "=r"(r[2]), "=r"(r[3]) : "r"(addr));
}
__device__ __forceinline__ float tanh_fast(float x) {
    const float e = __expf(2.f * x);
    return 1.f - __fdividef(2.f, e + 1.f);
}

// ---------------------------------------------------------------------------
// g_W1h[u][k] = half(W1[k][u])
// ---------------------------------------------------------------------------
__global__ void w1h_kernel(const float* __restrict__ W1) {
    __shared__ float sm[32][33];
    const int k0 = blockIdx.x * 32, u0 = blockIdx.y * 32;
    const int tx = threadIdx.x, ty = threadIdx.y;
#pragma unroll
    for (int j = 0; j < 4; ++j) {
        const int r = ty + j * 8;
        sm[r][tx] = W1[(size_t)(k0 + r) * UU + u0 + tx];
    }
    __syncthreads();
#pragma unroll
    for (int j = 0; j < 4; ++j) {
        const int r = ty + j * 8;
        g_W1h[(size_t)(u0 + r) * DD + k0 + tx] = __float2half_rn(sm[tx][r]);
    }
}

// ---------------------------------------------------------------------------
// hq[b][u] = query[b,:] @ W2[:,u] + b2[u] + b1[u]; also zeroes ctx (2 elems/thr)
// ---------------------------------------------------------------------------
__global__ void hq_kernel(const float* __restrict__ query,
                          const float* __restrict__ W2,
                          const float* __restrict__ b1,
                          const float* __restrict__ b2,
                          float* __restrict__ ctx) {
    __shared__ float q[DD];
    const int b = blockIdx.x;
    const int u = threadIdx.x;
    if (ctx) {
        const int i = b * 256 + u;
        ctx[2 * i] = 0.f;
        ctx[2 * i + 1] = 0.f;
    }
    for (int i = threadIdx.x; i < DD; i += blockDim.x) q[i] = query[b * DD + i];
    __syncthreads();
    float acc = b1[u] + b2[u];
#pragma unroll 8
    for (int d = 0; d < DD; ++d) acc = fmaf(q[d], W2[d * UU + u], acc);
    g_hq[b * UU + u] = acc;
}

// ---------------------------------------------------------------------------
// scores: fp16 mma.m16n8k16, 128t x 256u x 512k per CTA, 512 thr (2M x 8N),
// K-chunks of 64 (8 chunks), double-buffered cp.async(B)/reg-prefetch(A),
// ldmatrix fragment loads. smem ~111KB.
// ---------------------------------------------------------------------------
__global__ __launch_bounds__(512, 1)
void scores_mma(const float* __restrict__ values,
                const float* __restrict__ Vv) {
    extern __shared__ char smc[];
    __half* As   = (__half*)smc;                  // 2 x [128][APH] = 36864 B
    __half* Bs   = (__half*)(smc + 36864);        // 2 x [256][BPH] = 73728 B
    float*  sred = (float*)(smc + 110592);        // [128]
    const uint32_t As_u32 = smem_u32(As);
    const uint32_t Bs_u32 = smem_u32(Bs);

    const int b     = blockIdx.y;
    const int tbase = blockIdx.x * 128;
    const int tid   = threadIdx.x;
    const int lane  = tid & 31;
    const int wid   = tid >> 5;
    const int wm    = wid & 1;            // M half (64 rows each)
    const int wn    = wid >> 1;           // N: 8 x 32 u
    const int g     = lane >> 2;
    const int tg    = lane & 3;

    const int lrow = lane & 15;
    const int lk8  = (lane & 16) >> 1;    // 0 or 8 halves

    const float* vbase = values + ((size_t)b * TT + tbase) * DD;

    // staging coords: A 128r x 64k floats -> 2048 float4, 4/thread
    const int arow = tid >> 2;            // 0..127
    const int ak4  = (tid & 3) * 4;       // float4 col 0..15 step 4
    // B: 256u x 64k halves = 32KB -> 2048 x 16B, 4/thread
    const int ub   = tid >> 1;            // u 0..255
    const int hk   = (tid & 1) * 32;      // halves offset 0/32

    float acc[4][4][4];
#pragma unroll
    for (int i = 0; i < 4; ++i)
#pragma unroll
        for (int j = 0; j < 4; ++j)
#pragma unroll
            for (int c = 0; c < 4; ++c) acc[i][j][c] = 0.f;

    float4 pf[4];

    // ---- prologue: stage chunk 0 ----
    {
        const __half* w1p = g_W1h + (size_t)ub * DD + hk;
        const uint32_t bdst = Bs_u32 + (ub * BPH + hk) * 2;
#pragma unroll
        for (int x = 0; x < 4; ++x) cp_async16(bdst + x * 16, w1p + x * 8);
        cp_commit();
#pragma unroll
        for (int l = 0; l < 4; ++l)
            pf[l] = *(const float4*)(vbase + (size_t)arow * DD + (ak4 + l) * 4);
#pragma unroll
        for (int l = 0; l < 4; ++l) {
            __half2 pa = __floats2half2_rn(pf[l].x, pf[l].y);
            __half2 pb = __floats2half2_rn(pf[l].z, pf[l].w);
            *(uint2*)(As + arow * APH + (ak4 + l) * 4) =
                make_uint2(*(uint32_t*)&pa, *(uint32_t*)&pb);
        }
        cp_wait0();
    }
    __syncthreads();

    for (int c = 0; c < 8; ++c) {
        const int buf = c & 1;
        const int nxt = buf ^ 1;

        if (c < 7) {
            const int k0n = (c + 1) * 64;
            const __half* w1p = g_W1h + (size_t)ub * DD + k0n + hk;
            const uint32_t bdst = Bs_u32 + (nxt * 256 * BPH + ub * BPH + hk) * 2;
#pragma unroll
            for (int x = 0; x < 4; ++x) cp_async16(bdst + x * 16, w1p + x * 8);
            cp_commit();
#pragma unroll
            for (int l = 0; l < 4; ++l)
                pf[l] = *(const float4*)(vbase + (size_t)arow * DD + k0n + (ak4 + l) * 4);
        }

        // ---- compute chunk c (4 k16 steps) ----
        const uint32_t Abase = As_u32 + buf * 128 * APH * 2;
        const uint32_t Bbase = Bs_u32 + buf * 256 * BPH * 2;
#pragma unroll
        for (int ks = 0; ks < 4; ++ks) {
            const int kk = ks * 16;
            uint32_t a[4][4];
#pragma unroll
            for (int mi = 0; mi < 4; ++mi) {
                const int row = wm * 64 + mi * 16 + lrow;
                ldsm_x4(a[mi], Abase + (row * APH + kk + lk8) * 2);
            }
            uint32_t bf[4][2];
#pragma unroll
            for (int j = 0; j < 2; ++j) {
                uint32_t r[4];
                const int u = wn * 32 + j * 16 + lrow;
                ldsm_x4(r, Bbase + (u * BPH + kk + lk8) * 2);
                bf[2 * j][0]     = r[0];
                bf[2 * j + 1][0] = r[1];
                bf[2 * j][1]     = r[2];
                bf[2 * j + 1][1] = r[3];
            }
#pragma unroll
            for (int mi = 0; mi < 4; ++mi)
#pragma unroll
                for (int nj = 0; nj < 4; ++nj)
                    mma_f16(acc[mi][nj], a[mi], bf[nj]);
        }

        if (c < 7) {
            __half* An = As + nxt * 128 * APH;
#pragma unroll
            for (int l = 0; l < 4; ++l) {
                __half2 pa = __floats2half2_rn(pf[l].x, pf[l].y);
                __half2 pb = __floats2half2_rn(pf[l].z, pf[l].w);
                *(uint2*)(An + arow * APH + (ak4 + l) * 4) =
                    make_uint2(*(uint32_t*)&pa, *(uint32_t*)&pb);
            }
            cp_wait0();
            __syncthreads();
        }
    }

    // ---- epilogue: fast tanh + dot with V, reduce over u ----
    float sp[4][2];
#pragma unroll
    for (int mi = 0; mi < 4; ++mi) { sp[mi][0] = 0.f; sp[mi][1] = 0.f; }

#pragma unroll
    for (int nj = 0; nj < 4; ++nj) {
        const int u0  = wn * 32 + nj * 8 + 2 * tg;
        const float h0 = g_hq[b * UU + u0];
        const float h1 = g_hq[b * UU + u0 + 1];
        const float v0 = Vv[u0];
        const float v1 = Vv[u0 + 1];
#pragma unroll
        for (int mi = 0; mi < 4; ++mi) {
            sp[mi][0] = fmaf(tanh_fast(acc[mi][nj][0] + h0), v0, sp[mi][0]);
            sp[mi][0] = fmaf(tanh_fast(acc[mi][nj][1] + h1), v1, sp[mi][0]);
            sp[mi][1] = fmaf(tanh_fast(acc[mi][nj][2] + h0), v0, sp[mi][1]);
            sp[mi][1] = fmaf(tanh_fast(acc[mi][nj][3] + h1), v1, sp[mi][1]);
        }
    }
#pragma unroll
    for (int off = 1; off <= 2; off <<= 1)
#pragma unroll
        for (int mi = 0; mi < 4; ++mi) {
            sp[mi][0] += __shfl_xor_sync(0xffffffffu, sp[mi][0], off);
            sp[mi][1] += __shfl_xor_sync(0xffffffffu, sp[mi][1], off);
        }

    if (tid < 128) sred[tid] = 0.f;
    __syncthreads();
    if (tg == 0) {
#pragma unroll
        for (int mi = 0; mi < 4; ++mi) {
            atomicAdd(&sred[wm * 64 + mi * 16 + g],     sp[mi][0]);
            atomicAdd(&sred[wm * 64 + mi * 16 + g + 8], sp[mi][1]);
        }
    }
    __syncthreads();
    if (tid < 128) g_scores[(size_t)b * TT + tbase + tid] = sred[tid];
}

// ---------------------------------------------------------------------------
// softmax over T per batch; 1024 threads
// ---------------------------------------------------------------------------
__global__ void softmax_kernel(float* __restrict__ wout) {
    __shared__ float red[32];
    __shared__ float bcast;
    const int b   = blockIdx.x;
    const int tid = threadIdx.x;
    float* s = g_scores + (size_t)b * TT;

    float m = -3.4e38f;
    for (int i = tid; i < TT; i += 1024) m = fmaxf(m, s[i]);
#pragma unroll
    for (int off = 16; off; off >>= 1)
        m = fmaxf(m, __shfl_xor_sync(0xffffffffu, m, off));
    if ((tid & 31) == 0) red[tid >> 5] = m;
    __syncthreads();
    if (tid == 0) {
        float mm = red[0];
        for (int i = 1; i < 32; ++i) mm = fmaxf(mm, red[i]);
        bcast = mm;
    }
    __syncthreads();
    m = bcast;

    float sum = 0.f;
    for (int i = tid; i < TT; i += 1024) {
        const float e = expf(s[i] - m);
        s[i] = e;
        sum += e;
    }
#pragma unroll
    for (int off = 16; off; off >>= 1)
        sum += __shfl_xor_sync(0xffffffffu, sum, off);
    if ((tid & 31) == 0) red[tid >> 5] = sum;
    __syncthreads();
    if (tid == 0) {
        float t = 0.f;
        for (int i = 0; i < 32; ++i) t += red[i];
        bcast = 1.f / t;
    }
    __syncthreads();
    const float inv = bcast;

    for (int i = tid; i < TT; i += 1024) {
        const float wv = s[i] * inv;
        s[i] = wv;
        if (wout) wout[(size_t)b * TT + i] = wv;
    }
}

// ---------------------------------------------------------------------------
// context[b][d] = sum_t weights[b][t] * values[b][t][d]
// block 512 = 4 t-streams x 128 d4-lanes; smem cross-stream reduce; atomics.
// grid (16, BB)
// ---------------------------------------------------------------------------
__global__ __launch_bounds__(512, 2)
void ctx_kernel(const float* __restrict__ values,
                float* __restrict__ ctx) {
    __shared__ float4 sm4[4][128];
    const int b   = blockIdx.y;
    const int tid = threadIdx.x;
    const int d4  = tid & 127;
    const int grp = tid >> 7;              // 0..3
    const int tstart = blockIdx.x * (TT / 16);
    const float4* vb = (const float4*)(values + (size_t)b * TT * DD) + d4;
    const float*  w  = g_scores + (size_t)b * TT;

    float4 acc = make_float4(0.f, 0.f, 0.f, 0.f);
#pragma unroll 8
    for (int t = tstart + grp; t < tstart + TT / 16; t += 4) {
        const float wv = w[t];
        const float4 v = vb[(size_t)t * (DD / 4)];
        acc.x = fmaf(wv, v.x, acc.x);
        acc.y = fmaf(wv, v.y, acc.y);
        acc.z = fmaf(wv, v.z, acc.z);
        acc.w = fmaf(wv, v.w, acc.w);
    }
    sm4[grp][d4] = acc;
    __syncthreads();
    if (grp == 0) {
        const float4 a1 = sm4[1][d4], a2 = sm4[2][d4], a3 = sm4[3][d4];
        acc.x += a1.x + a2.x + a3.x;
        acc.y += a1.y + a2.y + a3.y;
        acc.z += a1.z + a2.z + a3.z;
        acc.w += a1.w + a2.w + a3.w;
        float* o = ctx + b * DD + d4 * 4;
        atomicAdd(o + 0, acc.x);
        atomicAdd(o + 1, acc.y);
        atomicAdd(o + 2, acc.z);
        atomicAdd(o + 3, acc.w);
    }
}

// ---------------------------------------------------------------------------
extern "C" void kernel_launch(void* const* d_in, const int* in_sizes, int n_in,
                              void* d_out, int out_size) {
    const float* values = (const float*)d_in[0];
    const float* query  = (const float*)d_in[1];
    const float* W1     = (const float*)d_in[2];
    const float* b1     = (const float*)d_in[3];
    const float* W2     = (const float*)d_in[4];
    const float* b2     = (const float*)d_in[5];
    const float* Vv     = (const float*)d_in[6];
    // d_in[7] = bV: constant logit shift, cancels exactly in softmax.

    float* out  = (float*)d_out;
    float* ctx  = nullptr;
    float* wout = nullptr;
    if (out_size >= BB * DD + BB * TT) {
        ctx  = out;
        wout = out + BB * DD;
    } else if (out_size == BB * TT) {
        wout = out;
    } else {
        ctx = out;
    }

    const int smem_bytes = 110592 + 128 * sizeof(float);
    cudaFuncSetAttribute(scores_mma, cudaFuncAttributeMaxDynamicSharedMemorySize,
                         smem_bytes);

    w1h_kernel<<<dim3(DD / 32, UU / 32), dim3(32, 8)>>>(W1);
    hq_kernel<<<BB, 256>>>(query, W2, b1, b2, ctx);
    scores_mma<<<dim3(TT / 128, BB), 512, smem_bytes>>>(values, Vv);
    softmax_kernel<<<BB, 1024>>>(wout);
    if (ctx) {
        ctx_kernel<<<dim3(16, BB), 512>>>(values, ctx);
    }
}

// round 9
// speedup vs baseline: 1.0798x; 1.0798x over previous
#include <cuda_runtime.h>
#include <cuda_fp16.h>
#include <math.h>
#include <stdint.h>

#define BB 32
#define TT 4096
#define DD 512
#define UU 256

#define APH 40    // As pitch in halves (32 k + 8 pad) -> 80B rows, LDSM-conflict-free
#define BPH 40    // Bs pitch in halves

// scratch (no allocations allowed)
__device__ float  g_hq[BB * UU];
__device__ float  g_scores[BB * TT];
__device__ __half g_W1h[UU * DD];   // W1 transposed [u][k], fp16

__device__ __forceinline__ uint32_t smem_u32(const void* p) {
    uint32_t a;
    asm("{ .reg .u64 t; cvta.to.shared.u64 t, %1; cvt.u32.u64 %0, t; }"
        : "=r"(a) : "l"(p));
    return a;
}
__device__ __forceinline__ void cp_async16(uint32_t dst, const void* src) {
    asm volatile("cp.async.cg.shared.global [%0], [%1], 16;"
                 :: "r"(dst), "l"(src) : "memory");
}
__device__ __forceinline__ void cp_commit() {
    asm volatile("cp.async.commit_group;" ::: "memory");
}
__device__ __forceinline__ void cp_wait0() {
    asm volatile("cp.async.wait_group 0;" ::: "memory");
}
__device__ __forceinline__ void mma_f16(float c[4], const uint32_t a[4],
                                        const uint32_t b[2]) {
    asm volatile(
        "mma.sync.aligned.m16n8k16.row.col.f32.f16.f16.f32 "
        "{%0,%1,%2,%3}, {%4,%5,%6,%7}, {%8,%9}, {%0,%1,%2,%3};"
        : "+f"(c[0]), "+f"(c[1]), "+f"(c[2]), "+f"(c[3])
        : "r"(a[0]), "r"(a[1]), "r"(a[2]), "r"(a[3]), "r"(b[0]), "r"(b[1]));
}
__device__ __forceinline__ void ldsm_x4(uint32_t r[4], uint32_t addr) {
    asm volatile("ldmatrix.sync.aligned.m8n8.x4.shared.b16 {%0,%1,%2,%3}, [%4];"
                 : "=r"(r[0]), "=r"(r[1]), "=r"(r[2]), "=r"(r[3]) : "r"(addr));
}
__device__ __forceinline__ float tanh_fast(float x) {
    const float e = __expf(2.f * x);
    return 1.f - __fdividef(2.f, e + 1.f);
}

// ---------------------------------------------------------------------------
// g_W1h[u][k] = half(W1[k][u])
// ---------------------------------------------------------------------------
__global__ void w1h_kernel(const float* __restrict__ W1) {
    __shared__ float sm[32][33];
    const int k0 = blockIdx.x * 32, u0 = blockIdx.y * 32;
    const int tx = threadIdx.x, ty = threadIdx.y;
#pragma unroll
    for (int j = 0; j < 4; ++j) {
        const int r = ty + j * 8;
        sm[r][tx] = W1[(size_t)(k0 + r) * UU + u0 + tx];
    }
    __syncthreads();
#pragma unroll
    for (int j = 0; j < 4; ++j) {
        const int r = ty + j * 8;
        g_W1h[(size_t)(u0 + r) * DD + k0 + tx] = __float2half_rn(sm[tx][r]);
    }
}

// ---------------------------------------------------------------------------
// hq[b][u] = query[b,:] @ W2[:,u] + b2[u] + b1[u]; also zeroes ctx
// ---------------------------------------------------------------------------
__global__ void hq_kernel(const float* __restrict__ query,
                          const float* __restrict__ W2,
                          const float* __restrict__ b1,
                          const float* __restrict__ b2,
                          float* __restrict__ ctx) {
    __shared__ float q[DD];
    const int b = blockIdx.x;
    const int u = threadIdx.x;
    if (ctx) {
        const int i = b * 256 + u;
        ctx[2 * i] = 0.f;
        ctx[2 * i + 1] = 0.f;
    }
    for (int i = threadIdx.x; i < DD; i += blockDim.x) q[i] = query[b * DD + i];
    __syncthreads();
    float acc = b1[u] + b2[u];
#pragma unroll 8
    for (int d = 0; d < DD; ++d) acc = fmaf(q[d], W2[d * UU + u], acc);
    g_hq[b * UU + u] = acc;
}

// ---------------------------------------------------------------------------
// scores: fp16 mma.m16n8k16, 128t x 256u x 512k per CTA, 512 thr (2M x 8N),
// K-chunks of 32, double-buffered cp.async(B)/reg-prefetch(A),
// ldmatrix fragment loads. (exact R6 configuration)
// ---------------------------------------------------------------------------
__global__ __launch_bounds__(512, 1)
void scores_mma(const float* __restrict__ values,
                const float* __restrict__ Vv) {
    extern __shared__ char smc[];
    __half* As   = (__half*)smc;                 // 2 x [128][APH]
    __half* Bs   = (__half*)(smc + 20480);       // 2 x [256][BPH]
    float*  sred = (float*)(smc + 61440);        // [128]
    const uint32_t As_u32 = smem_u32(As);
    const uint32_t Bs_u32 = smem_u32(Bs);

    const int b     = blockIdx.y;
    const int tbase = blockIdx.x * 128;
    const int tid   = threadIdx.x;
    const int lane  = tid & 31;
    const int wid   = tid >> 5;
    const int wm    = wid & 1;            // M half (64 rows each)
    const int wn    = wid >> 1;           // N: 8 x 32 u
    const int g     = lane >> 2;
    const int tg    = lane & 3;

    const int lrow = lane & 15;
    const int lk8  = (lane & 16) >> 1;    // 0 or 8 halves

    const float* vbase = values + ((size_t)b * TT + tbase) * DD;

    // staging coords
    const int at0 = tid >> 3;             // A rows at0, at0+64 ; col k4a*4 floats
    const int k4a = tid & 7;
    const int ub  = tid >> 1;             // B row u (0..255)
    const int hk  = (tid & 1) * 16;       // halves offset within 32-k row

    float acc[4][4][4];
#pragma unroll
    for (int i = 0; i < 4; ++i)
#pragma unroll
        for (int j = 0; j < 4; ++j)
#pragma unroll
            for (int c = 0; c < 4; ++c) acc[i][j][c] = 0.f;

    float4 pfA0, pfA1;

    // ---- prologue: stage chunk 0 ----
    {
        const __half* w1p = g_W1h + (size_t)ub * DD + hk;
        const uint32_t bdst = Bs_u32 + (ub * BPH + hk) * 2;
        cp_async16(bdst, w1p);
        cp_async16(bdst + 16, w1p + 8);
        cp_commit();
        pfA0 = *(const float4*)(vbase + (size_t)at0 * DD + k4a * 4);
        pfA1 = *(const float4*)(vbase + (size_t)(at0 + 64) * DD + k4a * 4);
        __half2 p0 = __floats2half2_rn(pfA0.x, pfA0.y);
        __half2 p1 = __floats2half2_rn(pfA0.z, pfA0.w);
        __half2 p2 = __floats2half2_rn(pfA1.x, pfA1.y);
        __half2 p3 = __floats2half2_rn(pfA1.z, pfA1.w);
        uint2 s0 = make_uint2(*(uint32_t*)&p0, *(uint32_t*)&p1);
        uint2 s1 = make_uint2(*(uint32_t*)&p2, *(uint32_t*)&p3);
        *(uint2*)(As + at0 * APH + k4a * 4) = s0;
        *(uint2*)(As + (at0 + 64) * APH + k4a * 4) = s1;
        cp_wait0();
    }
    __syncthreads();

    for (int c = 0; c < 16; ++c) {
        const int buf = c & 1;
        const int nxt = buf ^ 1;

        if (c < 15) {
            const int k0n = (c + 1) * 32;
            const __half* w1p = g_W1h + (size_t)ub * DD + k0n + hk;
            const uint32_t bdst = Bs_u32 + (nxt * 256 * BPH + ub * BPH + hk) * 2;
            cp_async16(bdst, w1p);
            cp_async16(bdst + 16, w1p + 8);
            cp_commit();
            pfA0 = *(const float4*)(vbase + (size_t)at0 * DD + k0n + k4a * 4);
            pfA1 = *(const float4*)(vbase + (size_t)(at0 + 64) * DD + k0n + k4a * 4);
        }

        // ---- compute chunk c (2 k16 steps), ldmatrix fragments ----
        const uint32_t Abase = As_u32 + buf * 128 * APH * 2;
        const uint32_t Bbase = Bs_u32 + buf * 256 * BPH * 2;
#pragma unroll
        for (int ks = 0; ks < 2; ++ks) {
            const int kk = ks * 16;
            uint32_t a[4][4];
#pragma unroll
            for (int mi = 0; mi < 4; ++mi) {
                const int row = wm * 64 + mi * 16 + lrow;
                ldsm_x4(a[mi], Abase + (row * APH + kk + lk8) * 2);
            }
            uint32_t bf[4][2];
#pragma unroll
            for (int j = 0; j < 2; ++j) {
                uint32_t r[4];
                const int u = wn * 32 + j * 16 + lrow;
                ldsm_x4(r, Bbase + (u * BPH + kk + lk8) * 2);
                bf[2 * j][0]     = r[0];
                bf[2 * j + 1][0] = r[1];
                bf[2 * j][1]     = r[2];
                bf[2 * j + 1][1] = r[3];
            }
#pragma unroll
            for (int mi = 0; mi < 4; ++mi)
#pragma unroll
                for (int nj = 0; nj < 4; ++nj)
                    mma_f16(acc[mi][nj], a[mi], bf[nj]);
        }

        if (c < 15) {
            __half* An = As + nxt * 128 * APH;
            __half2 p0 = __floats2half2_rn(pfA0.x, pfA0.y);
            __half2 p1 = __floats2half2_rn(pfA0.z, pfA0.w);
            __half2 p2 = __floats2half2_rn(pfA1.x, pfA1.y);
            __half2 p3 = __floats2half2_rn(pfA1.z, pfA1.w);
            uint2 s0 = make_uint2(*(uint32_t*)&p0, *(uint32_t*)&p1);
            uint2 s1 = make_uint2(*(uint32_t*)&p2, *(uint32_t*)&p3);
            *(uint2*)(An + at0 * APH + k4a * 4) = s0;
            *(uint2*)(An + (at0 + 64) * APH + k4a * 4) = s1;
            cp_wait0();
            __syncthreads();
        }
    }

    // ---- epilogue: fast tanh + dot with V, reduce over u ----
    float sp[4][2];
#pragma unroll
    for (int mi = 0; mi < 4; ++mi) { sp[mi][0] = 0.f; sp[mi][1] = 0.f; }

#pragma unroll
    for (int nj = 0; nj < 4; ++nj) {
        const int u0  = wn * 32 + nj * 8 + 2 * tg;
        const float h0 = g_hq[b * UU + u0];
        const float h1 = g_hq[b * UU + u0 + 1];
        const float v0 = Vv[u0];
        const float v1 = Vv[u0 + 1];
#pragma unroll
        for (int mi = 0; mi < 4; ++mi) {
            sp[mi][0] = fmaf(tanh_fast(acc[mi][nj][0] + h0), v0, sp[mi][0]);
            sp[mi][0] = fmaf(tanh_fast(acc[mi][nj][1] + h1), v1, sp[mi][0]);
            sp[mi][1] = fmaf(tanh_fast(acc[mi][nj][2] + h0), v0, sp[mi][1]);
            sp[mi][1] = fmaf(tanh_fast(acc[mi][nj][3] + h1), v1, sp[mi][1]);
        }
    }
#pragma unroll
    for (int off = 1; off <= 2; off <<= 1)
#pragma unroll
        for (int mi = 0; mi < 4; ++mi) {
            sp[mi][0] += __shfl_xor_sync(0xffffffffu, sp[mi][0], off);
            sp[mi][1] += __shfl_xor_sync(0xffffffffu, sp[mi][1], off);
        }

    if (tid < 128) sred[tid] = 0.f;
    __syncthreads();
    if (tg == 0) {
#pragma unroll
        for (int mi = 0; mi < 4; ++mi) {
            atomicAdd(&sred[wm * 64 + mi * 16 + g],     sp[mi][0]);
            atomicAdd(&sred[wm * 64 + mi * 16 + g + 8], sp[mi][1]);
        }
    }
    __syncthreads();
    if (tid < 128) g_scores[(size_t)b * TT + tbase + tid] = sred[tid];
}

// ---------------------------------------------------------------------------
// softmax over T per batch; 1024 threads
// ---------------------------------------------------------------------------
__global__ void softmax_kernel(float* __restrict__ wout) {
    __shared__ float red[32];
    __shared__ float bcast;
    const int b   = blockIdx.x;
    const int tid = threadIdx.x;
    float* s = g_scores + (size_t)b * TT;

    float m = -3.4e38f;
    for (int i = tid; i < TT; i += 1024) m = fmaxf(m, s[i]);
#pragma unroll
    for (int off = 16; off; off >>= 1)
        m = fmaxf(m, __shfl_xor_sync(0xffffffffu, m, off));
    if ((tid & 31) == 0) red[tid >> 5] = m;
    __syncthreads();
    if (tid == 0) {
        float mm = red[0];
        for (int i = 1; i < 32; ++i) mm = fmaxf(mm, red[i]);
        bcast = mm;
    }
    __syncthreads();
    m = bcast;

    float sum = 0.f;
    for (int i = tid; i < TT; i += 1024) {
        const float e = expf(s[i] - m);
        s[i] = e;
        sum += e;
    }
#pragma unroll
    for (int off = 16; off; off >>= 1)
        sum += __shfl_xor_sync(0xffffffffu, sum, off);
    if ((tid & 31) == 0) red[tid >> 5] = sum;
    __syncthreads();
    if (tid == 0) {
        float t = 0.f;
        for (int i = 0; i < 32; ++i) t += red[i];
        bcast = 1.f / t;
    }
    __syncthreads();
    const float inv = bcast;

    for (int i = tid; i < TT; i += 1024) {
        const float wv = s[i] * inv;
        s[i] = wv;
        if (wout) wout[(size_t)b * TT + i] = wv;
    }
}

// ---------------------------------------------------------------------------
// context[b][d] = sum_t weights[b][t] * values[b][t][d]
// block 512 = 4 t-streams x 128 d4-lanes; smem cross-stream reduce; atomics.
// grid (16, BB)
// ---------------------------------------------------------------------------
__global__ __launch_bounds__(512, 2)
void ctx_kernel(const float* __restrict__ values,
                float* __restrict__ ctx) {
    __shared__ float4 sm4[4][128];
    const int b   = blockIdx.y;
    const int tid = threadIdx.x;
    const int d4  = tid & 127;
    const int grp = tid >> 7;              // 0..3
    const int tstart = blockIdx.x * (TT / 16);
    const float4* vb = (const float4*)(values + (size_t)b * TT * DD) + d4;
    const float*  w  = g_scores + (size_t)b * TT;

    float4 acc = make_float4(0.f, 0.f, 0.f, 0.f);
#pragma unroll 8
    for (int t = tstart + grp; t < tstart + TT / 16; t += 4) {
        const float wv = w[t];
        const float4 v = vb[(size_t)t * (DD / 4)];
        acc.x = fmaf(wv, v.x, acc.x);
        acc.y = fmaf(wv, v.y, acc.y);
        acc.z = fmaf(wv, v.z, acc.z);
        acc.w = fmaf(wv, v.w, acc.w);
    }
    sm4[grp][d4] = acc;
    __syncthreads();
    if (grp == 0) {
        const float4 a1 = sm4[1][d4], a2 = sm4[2][d4], a3 = sm4[3][d4];
        acc.x += a1.x + a2.x + a3.x;
        acc.y += a1.y + a2.y + a3.y;
        acc.z += a1.z + a2.z + a3.z;
        acc.w += a1.w + a2.w + a3.w;
        float* o = ctx + b * DD + d4 * 4;
        atomicAdd(o + 0, acc.x);
        atomicAdd(o + 1, acc.y);
        atomicAdd(o + 2, acc.z);
        atomicAdd(o + 3, acc.w);
    }
}

// ---------------------------------------------------------------------------
extern "C" void kernel_launch(void* const* d_in, const int* in_sizes, int n_in,
                              void* d_out, int out_size) {
    const float* values = (const float*)d_in[0];
    const float* query  = (const float*)d_in[1];
    const float* W1     = (const float*)d_in[2];
    const float* b1     = (const float*)d_in[3];
    const float* W2     = (const float*)d_in[4];
    const float* b2     = (const float*)d_in[5];
    const float* Vv     = (const float*)d_in[6];
    // d_in[7] = bV: constant logit shift, cancels exactly in softmax.

    float* out  = (float*)d_out;
    float* ctx  = nullptr;
    float* wout = nullptr;
    if (out_size >= BB * DD + BB * TT) {
        ctx  = out;
        wout = out + BB * DD;
    } else if (out_size == BB * TT) {
        wout = out;
    } else {
        ctx = out;
    }

    const int smem_bytes = 61440 + 128 * sizeof(float);
    cudaFuncSetAttribute(scores_mma, cudaFuncAttributeMaxDynamicSharedMemorySize,
                         smem_bytes);

    w1h_kernel<<<dim3(DD / 32, UU / 32), dim3(32, 8)>>>(W1);
    hq_kernel<<<BB, 256>>>(query, W2, b1, b2, ctx);
    scores_mma<<<dim3(TT / 128, BB), 512, smem_bytes>>>(values, Vv);
    softmax_kernel<<<BB, 1024>>>(wout);
    if (ctx) {
        ctx_kernel<<<dim3(16, BB), 512>>>(values, ctx);
    }
}